// round 12
// baseline (speedup 1.0000x reference)
#include <cuda_runtime.h>
#include <cstdint>

// Problem dims (fixed by the reference setup)
#define NB 4      // batch
#define NQ 16     // queries used (of 20)
#define NQP 20    // queries stored in btn_dec
#define NT 8      // t
#define NHW 256   // h*w
#define HWT 8     // hw positions per tile (2 tiles per block)
#define QT 8      // q positions per block
#define NG 8      // heads

__device__ __forceinline__ void ffma2(unsigned long long& d,
                                      unsigned long long a,
                                      unsigned long long b) {
    asm("fma.rn.f32x2 %0, %1, %2, %0;" : "+l"(d) : "l"(a), "l"(b));
}
__device__ __forceinline__ unsigned long long pack2(float lo, float hi) {
    unsigned long long r;
    asm("mov.b64 %0, {%1, %2};" : "=l"(r) : "f"(lo), "f"(hi));
    return r;
}
__device__ __forceinline__ void unpack2(unsigned long long v, float& lo, float& hi) {
    asm("mov.b64 {%0, %1}, %2;" : "=f"(lo), "=f"(hi) : "l"(v));
}
// 16B async copy gmem -> smem (bypasses registers)
__device__ __forceinline__ void cp16(uint32_t saddr, const void* gptr) {
    asm volatile("cp.async.cg.shared.global [%0], [%1], 16;"
                 :: "r"(saddr), "l"(gptr));
}
__device__ __forceinline__ void cp_commit() {
    asm volatile("cp.async.commit_group;");
}
__device__ __forceinline__ void cp_wait_all() {
    asm volatile("cp.async.wait_group 0;");
}

// Swizzled float4-index within a 512-float row (head g, chunk c4 0..15):
// (c4+g)&15 skew -> conflict-free g-parallel reads, 1-cyc dec broadcasts.
__device__ __forceinline__ int sw_idx(int g, int c4) {
    return g * 16 + ((c4 + g) & 15);
}

// ---------------------------------------------------------------------------
// Fused kernel, cross-tile pipelined. Grid: 1024 blocks =
// (b:4) x (t:8) x (qh:2) x (hwpair:16), 128 threads, 52KB smem -> 4 blk/SM.
// Each block does TWO 8-hw tiles sharing one dec tile:
//   S(enc0+dec, cp.async) ; A(t0)->sc0              [store-idle, once/128rows]
//   B(t0) rows 0..31  ⊗ cp.async enc1               [stores flow]
//   B(t0) rows 32..63 ⊗ A(t1)->sc1                  [stores flow]
//   B(t1) rows 0..63                                [stores flow]
// ---------------------------------------------------------------------------
__global__ void __launch_bounds__(128, 4) heatmap_fused(
    const float* __restrict__ dec,   // (4, 20, 8, 512)
    const float* __restrict__ enc,   // (4, 8, 256, 512)
    const float* __restrict__ Wm,    // (8, 512)
    const float* __restrict__ bias,  // (512,)
    float* __restrict__ out)         // (4, 16, 8, 256, 512)
{
    extern __shared__ char smem_raw[];
    ulonglong2* dec_s  = reinterpret_cast<ulonglong2*>(smem_raw);            // 16 KB
    ulonglong2* enc_s0 = reinterpret_cast<ulonglong2*>(smem_raw + 16384);    // 16 KB
    ulonglong2* enc_s1 = reinterpret_cast<ulonglong2*>(smem_raw + 32768);    // 16 KB
    float*      sc0    = reinterpret_cast<float*>(smem_raw + 49152);         //  2 KB
    float*      sc1    = reinterpret_cast<float*>(smem_raw + 51200);         //  2 KB

    const int tid  = threadIdx.x;
    const int bid  = blockIdx.x;
    const int pair = bid & 15;           // covers hw [pair*16, pair*16+16)
    const int qh   = (bid >> 4) & 1;     // q0 = qh*8
    const int t    = (bid >> 5) & 7;
    const int b    = bid >> 8;
    const int hwb  = pair * 16;

    const uint32_t dec_sb  = (uint32_t)__cvta_generic_to_shared(dec_s);
    const uint32_t enc_sb0 = (uint32_t)__cvta_generic_to_shared(enc_s0);
    const uint32_t enc_sb1 = (uint32_t)__cvta_generic_to_shared(enc_s1);

    // ---- S: cp.async enc0 (8hw x 512) + dec (8q x 512), swizzled ----
    {
        const float* encg = enc + ((size_t)((b * NT + t) * NHW + hwb)) * 512;
#pragma unroll
        for (int k = 0; k < 8; k++) {
            int i = tid + k * 128;           // 0..1023
            int hwl = i >> 7;
            int j   = i & 127;
            cp16(enc_sb0 + (hwl * 128 + sw_idx(j >> 4, j & 15)) * 16,
                 encg + (size_t)i * 4);
        }
#pragma unroll
        for (int k = 0; k < 8; k++) {
            int i = tid + k * 128;           // 0..1023
            int q = i >> 7;                  // local q 0..7
            int j = i & 127;
            cp16(dec_sb + (q * 128 + sw_idx(j >> 4, j & 15)) * 16,
                 dec + ((size_t)((b * NQP + qh * QT + q) * NT + t)) * 512 + j * 4);
        }
        cp_commit();
    }

    // W/bias into registers while cp.async is in flight
    const int f4 = tid;
    const unsigned long long* W2 = reinterpret_cast<const unsigned long long*>(Wm);
    unsigned long long wreg[NG][2];
#pragma unroll
    for (int g = 0; g < NG; g++) {
        wreg[g][0] = W2[g * 256 + f4 * 2];
        wreg[g][1] = W2[g * 256 + f4 * 2 + 1];
    }
    const unsigned long long* B2 = reinterpret_cast<const unsigned long long*>(bias);
    const unsigned long long bb0 = B2[f4 * 2];
    const unsigned long long bb1 = B2[f4 * 2 + 1];

    cp_wait_all();
    __syncthreads();

    // Phase-A thread mapping: (qsub:2, hw:8, g:8), 4 q accumulators
    const int ga   = tid & 7;
    const int hwa  = (tid >> 3) & 7;
    const int qsub = tid >> 6;

    // ---- A(tile0) -> sc0 ----
    {
        unsigned long long acc[4];
#pragma unroll
        for (int q = 0; q < 4; q++) acc[q] = 0ull;
        const ulonglong2* erow = enc_s0 + hwa * 128;
        const ulonglong2* drow = dec_s + qsub * 4 * 128;
#pragma unroll 4
        for (int c4 = 0; c4 < 16; c4++) {
            const int cc = sw_idx(ga, c4);
            ulonglong2 e = erow[cc];
#pragma unroll
            for (int qq = 0; qq < 4; qq++) {
                ulonglong2 d = drow[qq * 128 + cc];
                ffma2(acc[qq], e.x, d.x);
                ffma2(acc[qq], e.y, d.y);
            }
        }
#pragma unroll
        for (int qq = 0; qq < 4; qq++) {
            float lo, hi;
            unpack2(acc[qq], lo, hi);
            sc0[((qsub * 4 + qq) * HWT + hwa) * NG + ga] = lo + hi;
        }
    }
    __syncthreads();

    // out float4 bases (q-local stride 262144, hwl stride 128)
    float4* outT0 = reinterpret_cast<float4*>(out)
        + ((size_t)((b * NQ + qh * QT) * NT + t) * NHW + hwb) * 128 + f4;
    float4* outT1 = outT0 + (size_t)HWT * 128;

#define B_ROW(scf, r, obase)                                                       \
    {                                                                              \
        float4 sA = (scf)[(r) * 2 + 0];                                            \
        float4 sB = (scf)[(r) * 2 + 1];                                            \
        unsigned long long a0 = bb0, a1 = bb1;                                     \
        unsigned long long sp;                                                     \
        sp = pack2(sA.x, sA.x); ffma2(a0, sp, wreg[0][0]); ffma2(a1, sp, wreg[0][1]); \
        sp = pack2(sA.y, sA.y); ffma2(a0, sp, wreg[1][0]); ffma2(a1, sp, wreg[1][1]); \
        sp = pack2(sA.z, sA.z); ffma2(a0, sp, wreg[2][0]); ffma2(a1, sp, wreg[2][1]); \
        sp = pack2(sA.w, sA.w); ffma2(a0, sp, wreg[3][0]); ffma2(a1, sp, wreg[3][1]); \
        sp = pack2(sB.x, sB.x); ffma2(a0, sp, wreg[4][0]); ffma2(a1, sp, wreg[4][1]); \
        sp = pack2(sB.y, sB.y); ffma2(a0, sp, wreg[5][0]); ffma2(a1, sp, wreg[5][1]); \
        sp = pack2(sB.z, sB.z); ffma2(a0, sp, wreg[6][0]); ffma2(a1, sp, wreg[6][1]); \
        sp = pack2(sB.w, sB.w); ffma2(a0, sp, wreg[7][0]); ffma2(a1, sp, wreg[7][1]); \
        float4 res;                                                                \
        asm("mov.b64 {%0, %1}, %2;" : "=f"(res.x), "=f"(res.y) : "l"(a0));         \
        asm("mov.b64 {%0, %1}, %2;" : "=f"(res.z), "=f"(res.w) : "l"(a1));         \
        res.x = fmaxf(res.x, 0.f);                                                 \
        res.y = fmaxf(res.y, 0.f);                                                 \
        res.z = fmaxf(res.z, 0.f);                                                 \
        res.w = fmaxf(res.w, 0.f);                                                 \
        const int q_   = (r) >> 3;                                                 \
        const int hwl_ = (r) & 7;                                                  \
        __stcs(&(obase)[(size_t)q_ * 262144 + hwl_ * 128], res);                   \
    }

    // ---- B(t0) rows 0..31  ⊗  cp.async enc1 staging ----
    {
        const float4* scf0 = reinterpret_cast<const float4*>(sc0);
        const float* encg1 = enc + ((size_t)((b * NT + t) * NHW + hwb + HWT)) * 512;
#pragma unroll 4
        for (int rr = 0; rr < 32; rr++) {
            if ((rr & 3) == 0) {
                int k = rr >> 2;                 // 0..7
                int i = tid + k * 128;           // 0..1023
                int hwl = i >> 7;
                int j   = i & 127;
                cp16(enc_sb1 + (hwl * 128 + sw_idx(j >> 4, j & 15)) * 16,
                     encg1 + (size_t)i * 4);
            }
            B_ROW(scf0, rr, outT0);
        }
        cp_commit();
        cp_wait_all();
    }
    __syncthreads();

    // ---- B(t0) rows 32..63  ⊗  A(tile1) -> sc1 ----
    {
        unsigned long long acc2[4];
#pragma unroll
        for (int q = 0; q < 4; q++) acc2[q] = 0ull;
        const ulonglong2* erow = enc_s1 + hwa * 128;
        const ulonglong2* drow = dec_s + qsub * 4 * 128;
        const float4* scf0 = reinterpret_cast<const float4*>(sc0);

#pragma unroll 2
        for (int s = 0; s < 16; s++) {
            const int cc = sw_idx(ga, s);
            ulonglong2 e = erow[cc];
#pragma unroll
            for (int qq = 0; qq < 4; qq++) {
                ulonglong2 d = drow[qq * 128 + cc];
                ffma2(acc2[qq], e.x, d.x);
                ffma2(acc2[qq], e.y, d.y);
            }
            B_ROW(scf0, 32 + s * 2 + 0, outT0);
            B_ROW(scf0, 32 + s * 2 + 1, outT0);
        }
#pragma unroll
        for (int qq = 0; qq < 4; qq++) {
            float lo, hi;
            unpack2(acc2[qq], lo, hi);
            sc1[((qsub * 4 + qq) * HWT + hwa) * NG + ga] = lo + hi;
        }
    }
    __syncthreads();

    // ---- B(t1) rows 0..63 ----
    {
        const float4* scf1 = reinterpret_cast<const float4*>(sc1);
#pragma unroll 4
        for (int r = 0; r < 64; r++) {
            B_ROW(scf1, r, outT1);
        }
    }
#undef B_ROW
}

extern "C" void kernel_launch(void* const* d_in, const int* in_sizes, int n_in,
                              void* d_out, int out_size)
{
    const float* dec  = (const float*)d_in[0];  // (4,20,8,512)
    const float* enc  = (const float*)d_in[1];  // (4,8,16,16,512)
    const float* Wm   = (const float*)d_in[2];  // (8,512)
    const float* bias = (const float*)d_in[3];  // (512,)
    float* out = (float*)d_out;                 // (4,16,8,16,16,512)

    const int smem = 52 * 1024;
    cudaFuncSetAttribute(heatmap_fused,
                         cudaFuncAttributeMaxDynamicSharedMemorySize, smem);

    // 1024 blocks = (b:4)x(t:8)x(qh:2)x(hwpair:16), 2 tiles each
    heatmap_fused<<<NB * NT * 2 * (NHW / 16), 128, smem>>>(dec, enc, Wm, bias, out);
}